// round 10
// baseline (speedup 1.0000x reference)
#include <cuda_runtime.h>
#include <cstdint>
#include <cstddef>

#define S_LEN 1024
#define D_DIM 64
#define BH    64   // B*H = 4*16

// Scratch: MK[bh][u][d] = sum_t mask[bh][u][t] * K[bh][t][d]   (16 MB)
static __device__ float g_MK[(size_t)BH * S_LEN * D_DIM];

// ---------------------------------------------------------------------------
// tf32 helpers
// ---------------------------------------------------------------------------
__device__ __forceinline__ uint32_t f2tf32(float f) {
    uint32_t u;
    asm("cvt.rna.tf32.f32 %0, %1;" : "=r"(u) : "f"(f));
    return u;
}

#define MMA_TF32(d, a, b) \
    asm volatile( \
        "mma.sync.aligned.m16n8k8.row.col.f32.tf32.tf32.f32 " \
        "{%0,%1,%2,%3}, {%4,%5,%6,%7}, {%8,%9}, {%0,%1,%2,%3};" \
        : "+f"((d)[0]), "+f"((d)[1]), "+f"((d)[2]), "+f"((d)[3]) \
        : "r"((a)[0]), "r"((a)[1]), "r"((a)[2]), "r"((a)[3]), \
          "r"((b)[0]), "r"((b)[1]))

__device__ __forceinline__ void split2(float f, float& hi, float& lo) {
    hi = __uint_as_float(f2tf32(f));
    lo = __uint_as_float(f2tf32(f - hi));
}

// ---------------------------------------------------------------------------
// K1/K3: tf32 mma batched GEMM NN: C[1024,64] = A[1024,1024] @ B[1024,64]
// Tile BM=128, BN=64, BK=16. 128 threads = 4 warps as 2(M)x2(N), warp 64x32.
// Register-prefetch double buffering on global loads.
// ---------------------------------------------------------------------------
#define A_PITCH 20
#define B_PITCH 72

__global__ __launch_bounds__(128) void gemm_tc_kernel(
    const float* __restrict__ A,
    const float* __restrict__ B,
    float* __restrict__ C)
{
    __shared__ float As[2][128][A_PITCH];   // [limb][m][k]
    __shared__ float Bs[2][16][B_PITCH];    // [limb][k][n]

    const int t    = threadIdx.x;
    const int wid  = t >> 5;
    const int lane = t & 31;
    const int wm   = wid & 1;      // 0..1  (64 rows each)
    const int wn   = wid >> 1;     // 0..1  (32 cols each)
    const int g    = lane >> 2;
    const int c    = lane & 3;

    const int bh = blockIdx.y;
    const int m0 = blockIdx.x * 128;

    const float* Ab = A + (size_t)bh * S_LEN * S_LEN;
    const float* Bb = B + (size_t)bh * S_LEN * D_DIM;
    float*       Cb = C + (size_t)bh * S_LEN * D_DIM;

    float acc[4][4][4];
#pragma unroll
    for (int i = 0; i < 4; i++)
#pragma unroll
        for (int j = 0; j < 4; j++)
#pragma unroll
            for (int q = 0; q < 4; q++) acc[i][j][q] = 0.0f;

    // prefetch registers
    float4 pa[4], pb[2];
    // A: 128x16 = 512 float4, 4/thread. r = idx>>2 (0..127), c4 = idx&3
    // B: 16x64  = 256 float4, 2/thread. 16 float4 per row: r = idx>>4 (0..15), c4 = idx&15

#define LOAD_TILE(k0) do { \
    _Pragma("unroll") \
    for (int p = 0; p < 4; p++) { \
        int idx = p * 128 + t; \
        int r = idx >> 2, c4 = idx & 3; \
        pa[p] = *(const float4*)&Ab[(size_t)(m0 + r) * S_LEN + (k0) + c4 * 4]; \
    } \
    _Pragma("unroll") \
    for (int p = 0; p < 2; p++) { \
        int idx = p * 128 + t; \
        int r = idx >> 4, c4 = idx & 15; \
        pb[p] = *(const float4*)&Bb[(size_t)((k0) + r) * D_DIM + c4 * 4]; \
    } \
} while (0)

#define STORE_TILE() do { \
    _Pragma("unroll") \
    for (int p = 0; p < 4; p++) { \
        int idx = p * 128 + t; \
        int r = idx >> 2, c4 = idx & 3; \
        float4 hi, lo; \
        split2(pa[p].x, hi.x, lo.x); split2(pa[p].y, hi.y, lo.y); \
        split2(pa[p].z, hi.z, lo.z); split2(pa[p].w, hi.w, lo.w); \
        *(float4*)&As[0][r][c4 * 4] = hi; \
        *(float4*)&As[1][r][c4 * 4] = lo; \
    } \
    _Pragma("unroll") \
    for (int p = 0; p < 2; p++) { \
        int idx = p * 128 + t; \
        int r = idx >> 4, c4 = idx & 15; \
        float4 hi, lo; \
        split2(pb[p].x, hi.x, lo.x); split2(pb[p].y, hi.y, lo.y); \
        split2(pb[p].z, hi.z, lo.z); split2(pb[p].w, hi.w, lo.w); \
        *(float4*)&Bs[0][r][c4 * 4] = hi; \
        *(float4*)&Bs[1][r][c4 * 4] = lo; \
    } \
} while (0)

    LOAD_TILE(0);
    STORE_TILE();
    __syncthreads();

    for (int kt = 0; kt < 64; kt++) {
        if (kt < 63) LOAD_TILE((kt + 1) * 16);

#pragma unroll
        for (int ks = 0; ks < 2; ks++) {
            const int kk = ks * 8;
            uint32_t a[2][4][4];
            uint32_t b[2][4][2];
#pragma unroll
            for (int l = 0; l < 2; l++)
#pragma unroll
                for (int mt = 0; mt < 4; mt++) {
                    int m = wm * 64 + mt * 16;
                    a[l][mt][0] = __float_as_uint(As[l][m + g][kk + c]);
                    a[l][mt][1] = __float_as_uint(As[l][m + g + 8][kk + c]);
                    a[l][mt][2] = __float_as_uint(As[l][m + g][kk + c + 4]);
                    a[l][mt][3] = __float_as_uint(As[l][m + g + 8][kk + c + 4]);
                }
#pragma unroll
            for (int l = 0; l < 2; l++)
#pragma unroll
                for (int nt = 0; nt < 4; nt++) {
                    int n = wn * 32 + nt * 8 + g;
                    b[l][nt][0] = __float_as_uint(Bs[l][kk + c][n]);
                    b[l][nt][1] = __float_as_uint(Bs[l][kk + c + 4][n]);
                }
#pragma unroll
            for (int mt = 0; mt < 4; mt++)
#pragma unroll
                for (int nt = 0; nt < 4; nt++) {
                    MMA_TF32(acc[mt][nt], a[0][mt], b[0][nt]);   // hh
                    MMA_TF32(acc[mt][nt], a[0][mt], b[1][nt]);   // h*lo
                    MMA_TF32(acc[mt][nt], a[1][mt], b[0][nt]);   // lo*h
                }
        }
        __syncthreads();
        if (kt < 63) {
            STORE_TILE();
            __syncthreads();
        }
    }

    // ---- epilogue ----
#pragma unroll
    for (int mt = 0; mt < 4; mt++)
#pragma unroll
        for (int nt = 0; nt < 4; nt++) {
            int row = m0 + wm * 64 + mt * 16 + g;
            int col = wn * 32 + nt * 8 + 2 * c;
            float2 v0 = make_float2(acc[mt][nt][0], acc[mt][nt][1]);
            float2 v1 = make_float2(acc[mt][nt][2], acc[mt][nt][3]);
            *(float2*)&Cb[(size_t)row * D_DIM + col]       = v0;
            *(float2*)&Cb[(size_t)(row + 8) * D_DIM + col] = v1;
        }
#undef LOAD_TILE
#undef STORE_TILE
}

// ---------------------------------------------------------------------------
// K2 (tensor cores): attn = softmax(scale * Q @ MK^T)
// CTA = 32 Q-rows x 1024 cols, 256 threads = 8 warps (all share the 32 rows;
// each warp owns a 32-col strip per 256-col chunk). tf32 2-limb.
// B operand (.col) reads B[n][k] k-contiguous == MK native layout (no transpose).
// ---------------------------------------------------------------------------
#define QP 68
#define K2_SMEM_BYTES ((2 * 32 * QP + 2 * 256 * QP) * 4)   // 156,672

__global__ __launch_bounds__(256, 1) void scores_softmax_tc(
    const float* __restrict__ Q,
    const float* __restrict__ MK,
    float* __restrict__ attn)
{
    extern __shared__ float sm[];
    float* Qh = sm;                 // [32][QP]
    float* Ql = sm + 32 * QP;
    float* Bh = sm + 2 * 32 * QP;   // [256][QP]
    float* Bl = Bh + 256 * QP;
    __shared__ float red[8][32];

    const int t    = threadIdx.x;
    const int wid  = t >> 5;        // 0..7 : col-strip owner
    const int lane = t & 31;
    const int g    = lane >> 2;
    const int c    = lane & 3;

    const int bh   = blockIdx.y;
    const int row0 = blockIdx.x * 32;

    const float* Qb  = Q  + (size_t)bh * S_LEN * D_DIM;
    const float* MKb = MK + (size_t)bh * S_LEN * D_DIM;

    // ---- load Q 32x64, scale, split ----
#pragma unroll
    for (int p = 0; p < 2; p++) {
        int idx = p * 256 + t;
        int r = idx >> 4, c4 = idx & 15;
        float4 v = *(const float4*)&Qb[(size_t)(row0 + r) * D_DIM + c4 * 4];
        float4 hi, lo;
        split2(v.x * 0.125f, hi.x, lo.x); split2(v.y * 0.125f, hi.y, lo.y);
        split2(v.z * 0.125f, hi.z, lo.z); split2(v.w * 0.125f, hi.w, lo.w);
        *(float4*)&Qh[r * QP + c4 * 4] = hi;
        *(float4*)&Ql[r * QP + c4 * 4] = lo;
    }
    __syncthreads();

    float acc[4][2][4][4];   // [chunk][mt][nt][reg]
#pragma unroll
    for (int i = 0; i < 4; i++)
#pragma unroll
        for (int j = 0; j < 2; j++)
#pragma unroll
            for (int q = 0; q < 4; q++)
#pragma unroll
                for (int r = 0; r < 4; r++) acc[i][j][q][r] = 0.0f;

    for (int nc = 0; nc < 4; nc++) {
        // load MK rows [nc*256, +256): native [n][k] layout, split
#pragma unroll
        for (int p = 0; p < 16; p++) {
            int idx = p * 256 + t;
            int r = idx >> 4, c4 = idx & 15;
            float4 v = *(const float4*)&MKb[(size_t)(nc * 256 + r) * D_DIM + c4 * 4];
            float4 hi, lo;
            split2(v.x, hi.x, lo.x); split2(v.y, hi.y, lo.y);
            split2(v.z, hi.z, lo.z); split2(v.w, hi.w, lo.w);
            *(float4*)&Bh[r * QP + c4 * 4] = hi;
            *(float4*)&Bl[r * QP + c4 * 4] = lo;
        }
        __syncthreads();

#pragma unroll
        for (int ks = 0; ks < 8; ks++) {
            const int kk = ks * 8;
            uint32_t a[2][2][4];
#pragma unroll
            for (int mt = 0; mt < 2; mt++) {
                int m = mt * 16;
                a[0][mt][0] = __float_as_uint(Qh[(m + g) * QP + kk + c]);
                a[0][mt][1] = __float_as_uint(Qh[(m + g + 8) * QP + kk + c]);
                a[0][mt][2] = __float_as_uint(Qh[(m + g) * QP + kk + c + 4]);
                a[0][mt][3] = __float_as_uint(Qh[(m + g + 8) * QP + kk + c + 4]);
                a[1][mt][0] = __float_as_uint(Ql[(m + g) * QP + kk + c]);
                a[1][mt][1] = __float_as_uint(Ql[(m + g + 8) * QP + kk + c]);
                a[1][mt][2] = __float_as_uint(Ql[(m + g) * QP + kk + c + 4]);
                a[1][mt][3] = __float_as_uint(Ql[(m + g + 8) * QP + kk + c + 4]);
            }
            uint32_t b[2][4][2];
#pragma unroll
            for (int nt = 0; nt < 4; nt++) {
                int n = wid * 32 + nt * 8 + g;
                b[0][nt][0] = __float_as_uint(Bh[n * QP + kk + c]);
                b[0][nt][1] = __float_as_uint(Bh[n * QP + kk + c + 4]);
                b[1][nt][0] = __float_as_uint(Bl[n * QP + kk + c]);
                b[1][nt][1] = __float_as_uint(Bl[n * QP + kk + c + 4]);
            }
#pragma unroll
            for (int mt = 0; mt < 2; mt++)
#pragma unroll
                for (int nt = 0; nt < 4; nt++) {
                    MMA_TF32(acc[nc][mt][nt], a[0][mt], b[0][nt]);
                    MMA_TF32(acc[nc][mt][nt], a[0][mt], b[1][nt]);
                    MMA_TF32(acc[nc][mt][nt], a[1][mt], b[0][nt]);
                }
        }
        __syncthreads();
    }

    // ---- softmax: rows per thread: mt*16+g (regs 0,1) and mt*16+g+8 (2,3) ----
    float fmax[2][2], fsum[2][2];
#pragma unroll
    for (int mt = 0; mt < 2; mt++)
#pragma unroll
        for (int h = 0; h < 2; h++) {
            float m = -1e30f;
#pragma unroll
            for (int nc = 0; nc < 4; nc++)
#pragma unroll
                for (int nt = 0; nt < 4; nt++) {
                    m = fmaxf(m, acc[nc][mt][nt][h * 2]);
                    m = fmaxf(m, acc[nc][mt][nt][h * 2 + 1]);
                }
            m = fmaxf(m, __shfl_xor_sync(0xFFFFFFFF, m, 1));
            m = fmaxf(m, __shfl_xor_sync(0xFFFFFFFF, m, 2));
            fmax[mt][h] = m;
        }
    if (c == 0) {
#pragma unroll
        for (int mt = 0; mt < 2; mt++)
#pragma unroll
            for (int h = 0; h < 2; h++)
                red[wid][mt * 16 + h * 8 + g] = fmax[mt][h];
    }
    __syncthreads();
#pragma unroll
    for (int mt = 0; mt < 2; mt++)
#pragma unroll
        for (int h = 0; h < 2; h++) {
            int row = mt * 16 + h * 8 + g;
            float m = red[0][row];
#pragma unroll
            for (int w = 1; w < 8; w++) m = fmaxf(m, red[w][row]);
            fmax[mt][h] = m;
        }
    __syncthreads();   // red reuse below

    // exp + sum
#pragma unroll
    for (int mt = 0; mt < 2; mt++)
#pragma unroll
        for (int h = 0; h < 2; h++) {
            float s = 0.0f;
            float m = fmax[mt][h];
#pragma unroll
            for (int nc = 0; nc < 4; nc++)
#pragma unroll
                for (int nt = 0; nt < 4; nt++) {
                    float e0 = __expf(acc[nc][mt][nt][h * 2] - m);
                    float e1 = __expf(acc[nc][mt][nt][h * 2 + 1] - m);
                    acc[nc][mt][nt][h * 2]     = e0;
                    acc[nc][mt][nt][h * 2 + 1] = e1;
                    s += e0 + e1;
                }
            s += __shfl_xor_sync(0xFFFFFFFF, s, 1);
            s += __shfl_xor_sync(0xFFFFFFFF, s, 2);
            fsum[mt][h] = s;
        }
    if (c == 0) {
#pragma unroll
        for (int mt = 0; mt < 2; mt++)
#pragma unroll
            for (int h = 0; h < 2; h++)
                red[wid][mt * 16 + h * 8 + g] = fsum[mt][h];
    }
    __syncthreads();
#pragma unroll
    for (int mt = 0; mt < 2; mt++)
#pragma unroll
        for (int h = 0; h < 2; h++) {
            int row = mt * 16 + h * 8 + g;
            float s = red[0][row];
#pragma unroll
            for (int w = 1; w < 8; w++) s += red[w][row];
            fsum[mt][h] = 1.0f / s;
        }

    // ---- write attn ----
    float* attnb = attn + ((size_t)bh * S_LEN + row0) * S_LEN;
#pragma unroll
    for (int nc = 0; nc < 4; nc++)
#pragma unroll
        for (int mt = 0; mt < 2; mt++)
#pragma unroll
            for (int nt = 0; nt < 4; nt++) {
                int col = nc * 256 + wid * 32 + nt * 8 + 2 * c;
                int r0 = mt * 16 + g;
                float2 v0 = make_float2(acc[nc][mt][nt][0] * fsum[mt][0],
                                        acc[nc][mt][nt][1] * fsum[mt][0]);
                float2 v1 = make_float2(acc[nc][mt][nt][2] * fsum[mt][1],
                                        acc[nc][mt][nt][3] * fsum[mt][1]);
                *(float2*)&attnb[(size_t)r0 * S_LEN + col]       = v0;
                *(float2*)&attnb[(size_t)(r0 + 8) * S_LEN + col] = v1;
            }
}

// ---------------------------------------------------------------------------
extern "C" void kernel_launch(void* const* d_in, const int* in_sizes, int n_in,
                              void* d_out, int out_size)
{
    const float* Q    = (const float*)d_in[0];
    const float* Kt   = (const float*)d_in[1];
    const float* V    = (const float*)d_in[2];
    const float* mask = (const float*)d_in[3];

    float* ctx  = (float*)d_out;                                  // [BH,1024,64]
    float* attn = ctx + (size_t)BH * S_LEN * D_DIM;               // [BH,1024,1024]

    void* mkptr = nullptr;
    cudaGetSymbolAddress(&mkptr, g_MK);
    float* MK = (float*)mkptr;

    cudaFuncSetAttribute(scores_softmax_tc,
                         cudaFuncAttributeMaxDynamicSharedMemorySize,
                         K2_SMEM_BYTES);

    // K1: MK = mask @ K
    gemm_tc_kernel<<<dim3(8, BH), 128>>>(mask, Kt, MK);
    // K2: attn = softmax(scale * Q @ MK^T)   (tensor cores + fused softmax)
    scores_softmax_tc<<<dim3(32, BH), 256, K2_SMEM_BYTES>>>(Q, MK, attn);
    // K3: ctx = attn @ V
    gemm_tc_kernel<<<dim3(8, BH), 128>>>(attn, V, ctx);
}

// round 12
// speedup vs baseline: 1.2468x; 1.2468x over previous
#include <cuda_runtime.h>
#include <cuda_fp16.h>
#include <cstdint>
#include <cstddef>

#define S_LEN 1024
#define D_DIM 64
#define BH    64   // B*H = 4*16

// Scratch: MK[bh][u][d] = sum_t mask[bh][u][t] * K[bh][t][d]   (16 MB)
static __device__ float g_MK[(size_t)BH * S_LEN * D_DIM];

// ---------------------------------------------------------------------------
// fp16 2-limb helpers
// ---------------------------------------------------------------------------
__device__ __forceinline__ void split2h(float f, __half& h, __half& l) {
    h = __float2half_rn(f);
    l = __float2half_rn(f - __half2float(h));
}
__device__ __forceinline__ uint32_t h2u(__half a, __half b) {
    __half2 p = __halves2half2(a, b);
    return *reinterpret_cast<uint32_t*>(&p);
}

// mma.m16n8k16 fp16 inputs, fp32 accum. C layout == m16n8k8 (c0=(g,2c) etc).
#define MMA_F16(d, a, b) \
    asm volatile( \
        "mma.sync.aligned.m16n8k16.row.col.f32.f16.f16.f32 " \
        "{%0,%1,%2,%3}, {%4,%5,%6,%7}, {%8,%9}, {%0,%1,%2,%3};" \
        : "+f"((d)[0]), "+f"((d)[1]), "+f"((d)[2]), "+f"((d)[3]) \
        : "r"((a)[0]), "r"((a)[1]), "r"((a)[2]), "r"((a)[3]), \
          "r"((b)[0]), "r"((b)[1]))

// ---------------------------------------------------------------------------
// K1/K3: fp16-limb mma batched GEMM NN: C[1024,64] = A[1024,1024] @ B[1024,64]
// Tile BM=128, BN=64, BK=16. 128 threads = 4 warps 2(M)x2(N), warp 64x32.
// A limbs smem [m][k] k-contig; B limbs transposed to [n][k] (col-operand).
// Register-prefetch double buffering on global loads.
// ---------------------------------------------------------------------------
#define AP 24   // fp16 pitch for [.][16] rows
#define BP 24

__global__ __launch_bounds__(128) void gemm_tc_kernel(
    const float* __restrict__ A,
    const float* __restrict__ B,
    float* __restrict__ C)
{
    __shared__ __half As[2][128][AP];   // [limb][m][k]
    __shared__ __half Bs[2][64][BP];    // [limb][n][k]

    const int t    = threadIdx.x;
    const int wid  = t >> 5;
    const int lane = t & 31;
    const int wm   = wid & 1;      // 0..1  (64 rows each)
    const int wn   = wid >> 1;     // 0..1  (32 cols each)
    const int g    = lane >> 2;
    const int c    = lane & 3;

    const int bh = blockIdx.y;
    const int m0 = blockIdx.x * 128;

    const float* Ab = A + (size_t)bh * S_LEN * S_LEN;
    const float* Bb = B + (size_t)bh * S_LEN * D_DIM;
    float*       Cb = C + (size_t)bh * S_LEN * D_DIM;

    float acc[4][4][4];
#pragma unroll
    for (int i = 0; i < 4; i++)
#pragma unroll
        for (int j = 0; j < 4; j++)
#pragma unroll
            for (int q = 0; q < 4; q++) acc[i][j][q] = 0.0f;

    float4 pa[4], pb[2];
    // A: 128x16 = 512 float4, 4/thread: r = idx>>2 (0..127), c4 = idx&3
    // B: 16x64  = 256 float4, 2/thread: r = idx>>4 (0..15),  c4 = idx&15

#define LOAD_TILE(k0) do { \
    _Pragma("unroll") \
    for (int p = 0; p < 4; p++) { \
        int idx = p * 128 + t; \
        int r = idx >> 2, c4 = idx & 3; \
        pa[p] = *(const float4*)&Ab[(size_t)(m0 + r) * S_LEN + (k0) + c4 * 4]; \
    } \
    _Pragma("unroll") \
    for (int p = 0; p < 2; p++) { \
        int idx = p * 128 + t; \
        int r = idx >> 4, c4 = idx & 15; \
        pb[p] = *(const float4*)&Bb[(size_t)((k0) + r) * D_DIM + c4 * 4]; \
    } \
} while (0)

#define STORE_TILE() do { \
    _Pragma("unroll") \
    for (int p = 0; p < 4; p++) { \
        int idx = p * 128 + t; \
        int r = idx >> 2, c4 = idx & 3; \
        __half h0,h1,h2,h3,l0,l1,l2,l3; \
        split2h(pa[p].x, h0, l0); split2h(pa[p].y, h1, l1); \
        split2h(pa[p].z, h2, l2); split2h(pa[p].w, h3, l3); \
        *(uint32_t*)&As[0][r][c4 * 4]     = h2u(h0, h1); \
        *(uint32_t*)&As[0][r][c4 * 4 + 2] = h2u(h2, h3); \
        *(uint32_t*)&As[1][r][c4 * 4]     = h2u(l0, l1); \
        *(uint32_t*)&As[1][r][c4 * 4 + 2] = h2u(l2, l3); \
    } \
    _Pragma("unroll") \
    for (int p = 0; p < 2; p++) { \
        int idx = p * 128 + t; \
        int r = idx >> 4, c4 = idx & 15;   /* r = k row, c4*4 = n base */ \
        float f[4] = {pb[p].x, pb[p].y, pb[p].z, pb[p].w}; \
        _Pragma("unroll") \
        for (int j = 0; j < 4; j++) { \
            __half h, l; split2h(f[j], h, l); \
            Bs[0][c4 * 4 + j][r] = h; \
            Bs[1][c4 * 4 + j][r] = l; \
        } \
    } \
} while (0)

    LOAD_TILE(0);
    STORE_TILE();
    __syncthreads();

    for (int kt = 0; kt < 64; kt++) {
        if (kt < 63) LOAD_TILE((kt + 1) * 16);

        uint32_t a[2][4][4];
        uint32_t b[2][4][2];
#pragma unroll
        for (int l = 0; l < 2; l++)
#pragma unroll
            for (int mt = 0; mt < 4; mt++) {
                int m = wm * 64 + mt * 16;
                a[l][mt][0] = *(const uint32_t*)&As[l][m + g][2 * c];
                a[l][mt][1] = *(const uint32_t*)&As[l][m + g + 8][2 * c];
                a[l][mt][2] = *(const uint32_t*)&As[l][m + g][2 * c + 8];
                a[l][mt][3] = *(const uint32_t*)&As[l][m + g + 8][2 * c + 8];
            }
#pragma unroll
        for (int l = 0; l < 2; l++)
#pragma unroll
            for (int nt = 0; nt < 4; nt++) {
                int n = wn * 32 + nt * 8 + g;
                b[l][nt][0] = *(const uint32_t*)&Bs[l][n][2 * c];
                b[l][nt][1] = *(const uint32_t*)&Bs[l][n][2 * c + 8];
            }
#pragma unroll
        for (int mt = 0; mt < 4; mt++)
#pragma unroll
            for (int nt = 0; nt < 4; nt++) {
                MMA_F16(acc[mt][nt], a[0][mt], b[0][nt]);   // hh
                MMA_F16(acc[mt][nt], a[0][mt], b[1][nt]);   // h*lo
                MMA_F16(acc[mt][nt], a[1][mt], b[0][nt]);   // lo*h
            }
        __syncthreads();
        if (kt < 63) {
            STORE_TILE();
            __syncthreads();
        }
    }

    // ---- epilogue ----
#pragma unroll
    for (int mt = 0; mt < 4; mt++)
#pragma unroll
        for (int nt = 0; nt < 4; nt++) {
            int row = m0 + wm * 64 + mt * 16 + g;
            int col = wn * 32 + nt * 8 + 2 * c;
            float2 v0 = make_float2(acc[mt][nt][0], acc[mt][nt][1]);
            float2 v1 = make_float2(acc[mt][nt][2], acc[mt][nt][3]);
            *(float2*)&Cb[(size_t)row * D_DIM + col]       = v0;
            *(float2*)&Cb[(size_t)(row + 8) * D_DIM + col] = v1;
        }
#undef LOAD_TILE
#undef STORE_TILE
}

// ---------------------------------------------------------------------------
// K2 (fp16-limb tensor cores): attn = softmax(scale * Q @ MK^T)
// CTA = 32 Q-rows x 1024 cols, 256 threads = 8 warps, each warp a 32-col strip
// per 256-col chunk. B operand reads MK native [n][k] layout (no transpose).
// ---------------------------------------------------------------------------
#define QP2 72   // fp16 pitch for [.][64] rows
#define K2_SMEM_BYTES ((2 * 32 * QP2 + 2 * 256 * QP2) * 2)   // 82,944

__global__ __launch_bounds__(256, 1) void scores_softmax_tc(
    const float* __restrict__ Q,
    const float* __restrict__ MK,
    float* __restrict__ attn)
{
    extern __shared__ __half smh[];
    __half* Qh = smh;                   // [32][QP2]
    __half* Ql = Qh + 32 * QP2;
    __half* Bh = Ql + 32 * QP2;         // [256][QP2]
    __half* Bl = Bh + 256 * QP2;
    __shared__ float red[8][32];

    const int t    = threadIdx.x;
    const int wid  = t >> 5;        // 0..7 : col-strip owner
    const int lane = t & 31;
    const int g    = lane >> 2;
    const int c    = lane & 3;

    const int bh   = blockIdx.y;
    const int row0 = blockIdx.x * 32;

    const float* Qb  = Q  + (size_t)bh * S_LEN * D_DIM;
    const float* MKb = MK + (size_t)bh * S_LEN * D_DIM;

    // ---- load Q 32x64, scale, split into fp16 limbs ----
#pragma unroll
    for (int p = 0; p < 2; p++) {
        int idx = p * 256 + t;
        int r = idx >> 4, c4 = idx & 15;
        float4 v = *(const float4*)&Qb[(size_t)(row0 + r) * D_DIM + c4 * 4];
        __half h0,h1,h2,h3,l0,l1,l2,l3;
        split2h(v.x * 0.125f, h0, l0); split2h(v.y * 0.125f, h1, l1);
        split2h(v.z * 0.125f, h2, l2); split2h(v.w * 0.125f, h3, l3);
        *(uint32_t*)&Qh[r * QP2 + c4 * 4]     = h2u(h0, h1);
        *(uint32_t*)&Qh[r * QP2 + c4 * 4 + 2] = h2u(h2, h3);
        *(uint32_t*)&Ql[r * QP2 + c4 * 4]     = h2u(l0, l1);
        *(uint32_t*)&Ql[r * QP2 + c4 * 4 + 2] = h2u(l2, l3);
    }
    __syncthreads();

    float acc[4][2][4][4];   // [chunk][mt][nt][reg]
#pragma unroll
    for (int i = 0; i < 4; i++)
#pragma unroll
        for (int j = 0; j < 2; j++)
#pragma unroll
            for (int q = 0; q < 4; q++)
#pragma unroll
                for (int r = 0; r < 4; r++) acc[i][j][q][r] = 0.0f;

    for (int nc = 0; nc < 4; nc++) {
        // load MK rows [nc*256, +256): native [n][k] layout, split
#pragma unroll
        for (int p = 0; p < 16; p++) {
            int idx = p * 256 + t;
            int r = idx >> 4, c4 = idx & 15;
            float4 v = *(const float4*)&MKb[(size_t)(nc * 256 + r) * D_DIM + c4 * 4];
            __half h0,h1,h2,h3,l0,l1,l2,l3;
            split2h(v.x, h0, l0); split2h(v.y, h1, l1);
            split2h(v.z, h2, l2); split2h(v.w, h3, l3);
            *(uint32_t*)&Bh[r * QP2 + c4 * 4]     = h2u(h0, h1);
            *(uint32_t*)&Bh[r * QP2 + c4 * 4 + 2] = h2u(h2, h3);
            *(uint32_t*)&Bl[r * QP2 + c4 * 4]     = h2u(l0, l1);
            *(uint32_t*)&Bl[r * QP2 + c4 * 4 + 2] = h2u(l2, l3);
        }
        __syncthreads();

#pragma unroll
        for (int ks = 0; ks < 4; ks++) {
            const int kk = ks * 16;
            uint32_t a[2][2][4];
#pragma unroll
            for (int mt = 0; mt < 2; mt++) {
                int m = mt * 16;
                a[0][mt][0] = *(const uint32_t*)&Qh[(m + g) * QP2 + kk + 2 * c];
                a[0][mt][1] = *(const uint32_t*)&Qh[(m + g + 8) * QP2 + kk + 2 * c];
                a[0][mt][2] = *(const uint32_t*)&Qh[(m + g) * QP2 + kk + 2 * c + 8];
                a[0][mt][3] = *(const uint32_t*)&Qh[(m + g + 8) * QP2 + kk + 2 * c + 8];
                a[1][mt][0] = *(const uint32_t*)&Ql[(m + g) * QP2 + kk + 2 * c];
                a[1][mt][1] = *(const uint32_t*)&Ql[(m + g + 8) * QP2 + kk + 2 * c];
                a[1][mt][2] = *(const uint32_t*)&Ql[(m + g) * QP2 + kk + 2 * c + 8];
                a[1][mt][3] = *(const uint32_t*)&Ql[(m + g + 8) * QP2 + kk + 2 * c + 8];
            }
            uint32_t b[2][4][2];
#pragma unroll
            for (int nt = 0; nt < 4; nt++) {
                int n = wid * 32 + nt * 8 + g;
                b[0][nt][0] = *(const uint32_t*)&Bh[n * QP2 + kk + 2 * c];
                b[0][nt][1] = *(const uint32_t*)&Bh[n * QP2 + kk + 2 * c + 8];
                b[1][nt][0] = *(const uint32_t*)&Bl[n * QP2 + kk + 2 * c];
                b[1][nt][1] = *(const uint32_t*)&Bl[n * QP2 + kk + 2 * c + 8];
            }
#pragma unroll
            for (int mt = 0; mt < 2; mt++)
#pragma unroll
                for (int nt = 0; nt < 4; nt++) {
                    MMA_F16(acc[nc][mt][nt], a[0][mt], b[0][nt]);
                    MMA_F16(acc[nc][mt][nt], a[0][mt], b[1][nt]);
                    MMA_F16(acc[nc][mt][nt], a[1][mt], b[0][nt]);
                }
        }
        __syncthreads();
    }

    // ---- softmax: rows per thread: mt*16+g (regs 0,1) and mt*16+g+8 (2,3) ----
    float fmax[2][2], fsum[2][2];
#pragma unroll
    for (int mt = 0; mt < 2; mt++)
#pragma unroll
        for (int h = 0; h < 2; h++) {
            float m = -1e30f;
#pragma unroll
            for (int nc = 0; nc < 4; nc++)
#pragma unroll
                for (int nt = 0; nt < 4; nt++) {
                    m = fmaxf(m, acc[nc][mt][nt][h * 2]);
                    m = fmaxf(m, acc[nc][mt][nt][h * 2 + 1]);
                }
            m = fmaxf(m, __shfl_xor_sync(0xFFFFFFFF, m, 1));
            m = fmaxf(m, __shfl_xor_sync(0xFFFFFFFF, m, 2));
            fmax[mt][h] = m;
        }
    if (c == 0) {
#pragma unroll
        for (int mt = 0; mt < 2; mt++)
#pragma unroll
            for (int h = 0; h < 2; h++)
                red[wid][mt * 16 + h * 8 + g] = fmax[mt][h];
    }
    __syncthreads();
#pragma unroll
    for (int mt = 0; mt < 2; mt++)
#pragma unroll
        for (int h = 0; h < 2; h++) {
            int row = mt * 16 + h * 8 + g;
            float m = red[0][row];
#pragma unroll
            for (int w = 1; w < 8; w++) m = fmaxf(m, red[w][row]);
            fmax[mt][h] = m;
        }
    __syncthreads();   // red reuse below

    // exp + sum
#pragma unroll
    for (int mt = 0; mt < 2; mt++)
#pragma unroll
        for (int h = 0; h < 2; h++) {
            float s = 0.0f;
            float m = fmax[mt][h];
#pragma unroll
            for (int nc = 0; nc < 4; nc++)
#pragma unroll
                for (int nt = 0; nt < 4; nt++) {
                    float e0 = __expf(acc[nc][mt][nt][h * 2] - m);
                    float e1 = __expf(acc[nc][mt][nt][h * 2 + 1] - m);
                    acc[nc][mt][nt][h * 2]     = e0;
                    acc[nc][mt][nt][h * 2 + 1] = e1;
                    s += e0 + e1;
                }
            s += __shfl_xor_sync(0xFFFFFFFF, s, 1);
            s += __shfl_xor_sync(0xFFFFFFFF, s, 2);
            fsum[mt][h] = s;
        }
    if (c == 0) {
#pragma unroll
        for (int mt = 0; mt < 2; mt++)
#pragma unroll
            for (int h = 0; h < 2; h++)
                red[wid][mt * 16 + h * 8 + g] = fsum[mt][h];
    }
    __syncthreads();
#pragma unroll
    for (int mt = 0; mt < 2; mt++)
#pragma unroll
        for (int h = 0; h < 2; h++) {
            int row = mt * 16 + h * 8 + g;
            float s = red[0][row];
#pragma unroll
            for (int w = 1; w < 8; w++) s += red[w][row];
            fsum[mt][h] = 1.0f / s;
        }

    // ---- write attn ----
    float* attnb = attn + ((size_t)bh * S_LEN + row0) * S_LEN;
#pragma unroll
    for (int nc = 0; nc < 4; nc++)
#pragma unroll
        for (int mt = 0; mt < 2; mt++)
#pragma unroll
            for (int nt = 0; nt < 4; nt++) {
                int col = nc * 256 + wid * 32 + nt * 8 + 2 * c;
                int r0 = mt * 16 + g;
                float2 v0 = make_float2(acc[nc][mt][nt][0] * fsum[mt][0],
                                        acc[nc][mt][nt][1] * fsum[mt][0]);
                float2 v1 = make_float2(acc[nc][mt][nt][2] * fsum[mt][1],
                                        acc[nc][mt][nt][3] * fsum[mt][1]);
                *(float2*)&attnb[(size_t)r0 * S_LEN + col]       = v0;
                *(float2*)&attnb[(size_t)(r0 + 8) * S_LEN + col] = v1;
            }
}

// ---------------------------------------------------------------------------
extern "C" void kernel_launch(void* const* d_in, const int* in_sizes, int n_in,
                              void* d_out, int out_size)
{
    const float* Q    = (const float*)d_in[0];
    const float* Kt   = (const float*)d_in[1];
    const float* V    = (const float*)d_in[2];
    const float* mask = (const float*)d_in[3];

    float* ctx  = (float*)d_out;                                  // [BH,1024,64]
    float* attn = ctx + (size_t)BH * S_LEN * D_DIM;               // [BH,1024,1024]

    void* mkptr = nullptr;
    cudaGetSymbolAddress(&mkptr, g_MK);
    float* MK = (float*)mkptr;

    cudaFuncSetAttribute(scores_softmax_tc,
                         cudaFuncAttributeMaxDynamicSharedMemorySize,
                         K2_SMEM_BYTES);

    // K1: MK = mask @ K        (fp16 2-limb mma)
    gemm_tc_kernel<<<dim3(8, BH), 128>>>(mask, Kt, MK);
    // K2: attn = softmax(scale * Q @ MK^T)   (fp16 2-limb mma + fused softmax)
    scores_softmax_tc<<<dim3(32, BH), 256, K2_SMEM_BYTES>>>(Q, MK, attn);
    // K3: ctx = attn @ V       (fp16 2-limb mma)
    gemm_tc_kernel<<<dim3(8, BH), 128>>>(attn, V, ctx);
}

// round 17
// speedup vs baseline: 1.2783x; 1.0252x over previous
#include <cuda_runtime.h>
#include <cuda_fp16.h>
#include <cstdint>
#include <cstddef>

#define S_LEN 1024
#define D_DIM 64
#define BH    64   // B*H = 4*16

// Scratch: MK[bh][u][d] = sum_t mask[bh][u][t] * K[bh][t][d]   (16 MB)
static __device__ float g_MK[(size_t)BH * S_LEN * D_DIM];

// ---------------------------------------------------------------------------
// helpers
// ---------------------------------------------------------------------------
__device__ __forceinline__ void split2h(float f, __half& h, __half& l) {
    h = __float2half_rn(f);
    l = __float2half_rn(f - __half2float(h));
}
__device__ __forceinline__ uint32_t h2u(__half a, __half b) {
    __half2 p = __halves2half2(a, b);
    return *reinterpret_cast<uint32_t*>(&p);
}
__device__ __forceinline__ uint32_t smem_u32(const void* p) {
    return (uint32_t)__cvta_generic_to_shared(p);
}

#define MMA_F16(d, a, b) \
    asm volatile( \
        "mma.sync.aligned.m16n8k16.row.col.f32.f16.f16.f32 " \
        "{%0,%1,%2,%3}, {%4,%5,%6,%7}, {%8,%9}, {%0,%1,%2,%3};" \
        : "+f"((d)[0]), "+f"((d)[1]), "+f"((d)[2]), "+f"((d)[3]) \
        : "r"((a)[0]), "r"((a)[1]), "r"((a)[2]), "r"((a)[3]), \
          "r"((b)[0]), "r"((b)[1]))

#define LDMX4(r, addr) \
    asm volatile("ldmatrix.sync.aligned.m8n8.x4.shared.b16 {%0,%1,%2,%3}, [%4];" \
        : "=r"((r)[0]), "=r"((r)[1]), "=r"((r)[2]), "=r"((r)[3]) : "r"(addr))
#define LDMX2(r, addr) \
    asm volatile("ldmatrix.sync.aligned.m8n8.x2.shared.b16 {%0,%1}, [%2];" \
        : "=r"((r)[0]), "=r"((r)[1]) : "r"(addr))

// ---------------------------------------------------------------------------
// K1/K3: fp16-limb mma batched GEMM NN: C[1024,64] = A[1024,1024] @ B[1024,64]
// BM=128, BN=64, BK=16. 128 threads = 4 warps 2(M)x2(N), warp 64x32.
// Double-buffered smem (1 sync/iter), ldmatrix fragment loads.
// ---------------------------------------------------------------------------
#define AP 24   // halves per A row (48 B, 16B-aligned, conflict-free)
#define BP 24

#define A_LIMB_B (128 * AP * 2)        // 6144 B
#define A_BUF_B  (2 * A_LIMB_B)        // 12288 B
#define B_LIMB_B (64 * BP * 2)         // 3072 B
#define B_BUF_B  (2 * B_LIMB_B)        // 6144 B

__global__ __launch_bounds__(128) void gemm_tc_kernel(
    const float* __restrict__ A,
    const float* __restrict__ B,
    float* __restrict__ C)
{
    __shared__ __half As[2][2][128][AP];   // [buf][limb][m][k]
    __shared__ __half Bs[2][2][64][BP];    // [buf][limb][n][k]

    const int t    = threadIdx.x;
    const int wid  = t >> 5;
    const int lane = t & 31;
    const int wm   = wid & 1;      // 64 rows each
    const int wn   = wid >> 1;     // 32 cols each
    const int g    = lane >> 2;
    const int c    = lane & 3;

    const int bh = blockIdx.y;
    const int m0 = blockIdx.x * 128;

    const float* Ab = A + (size_t)bh * S_LEN * S_LEN;
    const float* Bb = B + (size_t)bh * S_LEN * D_DIM;
    float*       Cb = C + (size_t)bh * S_LEN * D_DIM;

    float acc[4][4][4];
#pragma unroll
    for (int i = 0; i < 4; i++)
#pragma unroll
        for (int j = 0; j < 4; j++)
#pragma unroll
            for (int q = 0; q < 4; q++) acc[i][j][q] = 0.0f;

    // ldmatrix per-thread addresses (buf 0)
    const uint32_t as0 = smem_u32(&As[0][0][0][0]);
    const uint32_t bs0 = smem_u32(&Bs[0][0][0][0]);
    uint32_t a_addr[2][4], b_addr[2][4];
#pragma unroll
    for (int l = 0; l < 2; l++)
#pragma unroll
        for (int mt = 0; mt < 4; mt++) {
            int row = wm * 64 + mt * 16 + (lane & 15);
            a_addr[l][mt] = as0 + l * A_LIMB_B + (row * AP + (lane >> 4) * 8) * 2;
        }
#pragma unroll
    for (int l = 0; l < 2; l++)
#pragma unroll
        for (int nt = 0; nt < 4; nt++) {
            int n = wn * 32 + nt * 8 + (lane & 7);
            b_addr[l][nt] = bs0 + l * B_LIMB_B + (n * BP + ((lane >> 3) & 1) * 8) * 2;
        }

    float4 pa[4], pb[2];
    // A: 128x16 = 512 float4, 4/thread: r = idx>>2, c4 = idx&3
    // B: 16x64  = 256 float4, 2/thread: r = idx>>4, c4 = idx&15

#define LOAD_TILE(k0) do { \
    _Pragma("unroll") \
    for (int p = 0; p < 4; p++) { \
        int idx = p * 128 + t; \
        int r = idx >> 2, c4 = idx & 3; \
        pa[p] = *(const float4*)&Ab[(size_t)(m0 + r) * S_LEN + (k0) + c4 * 4]; \
    } \
    _Pragma("unroll") \
    for (int p = 0; p < 2; p++) { \
        int idx = p * 128 + t; \
        int r = idx >> 4, c4 = idx & 15; \
        pb[p] = *(const float4*)&Bb[(size_t)((k0) + r) * D_DIM + c4 * 4]; \
    } \
} while (0)

#define STORE_TILE(buf) do { \
    _Pragma("unroll") \
    for (int p = 0; p < 4; p++) { \
        int idx = p * 128 + t; \
        int r = idx >> 2, c4 = idx & 3; \
        __half h0,h1,h2,h3,l0,l1,l2,l3; \
        split2h(pa[p].x, h0, l0); split2h(pa[p].y, h1, l1); \
        split2h(pa[p].z, h2, l2); split2h(pa[p].w, h3, l3); \
        *(uint32_t*)&As[buf][0][r][c4 * 4]     = h2u(h0, h1); \
        *(uint32_t*)&As[buf][0][r][c4 * 4 + 2] = h2u(h2, h3); \
        *(uint32_t*)&As[buf][1][r][c4 * 4]     = h2u(l0, l1); \
        *(uint32_t*)&As[buf][1][r][c4 * 4 + 2] = h2u(l2, l3); \
    } \
    _Pragma("unroll") \
    for (int p = 0; p < 2; p++) { \
        int idx = p * 128 + t; \
        int r = idx >> 4, c4 = idx & 15; \
        float f[4] = {pb[p].x, pb[p].y, pb[p].z, pb[p].w}; \
        _Pragma("unroll") \
        for (int j = 0; j < 4; j++) { \
            __half h, l; split2h(f[j], h, l); \
            Bs[buf][0][c4 * 4 + j][r] = h; \
            Bs[buf][1][c4 * 4 + j][r] = l; \
        } \
    } \
} while (0)

    LOAD_TILE(0);
    STORE_TILE(0);
    __syncthreads();

    int cur = 0;
    for (int kt = 0; kt < 64; kt++) {
        if (kt < 63) LOAD_TILE((kt + 1) * 16);

        const uint32_t aoff = cur ? A_BUF_B : 0u;
        const uint32_t boff = cur ? B_BUF_B : 0u;
        uint32_t a[2][4][4];
        uint32_t b[2][4][2];
#pragma unroll
        for (int l = 0; l < 2; l++)
#pragma unroll
            for (int mt = 0; mt < 4; mt++)
                LDMX4(a[l][mt], a_addr[l][mt] + aoff);
#pragma unroll
        for (int l = 0; l < 2; l++)
#pragma unroll
            for (int nt = 0; nt < 4; nt++)
                LDMX2(b[l][nt], b_addr[l][nt] + boff);

#pragma unroll
        for (int mt = 0; mt < 4; mt++)
#pragma unroll
            for (int nt = 0; nt < 4; nt++) {
                MMA_F16(acc[mt][nt], a[0][mt], b[0][nt]);   // hh
                MMA_F16(acc[mt][nt], a[0][mt], b[1][nt]);   // h*lo
                MMA_F16(acc[mt][nt], a[1][mt], b[0][nt]);   // lo*h
            }

        if (kt < 63) {
            STORE_TILE(1 - cur);
            __syncthreads();
            cur ^= 1;
        }
    }

    // ---- epilogue ----
#pragma unroll
    for (int mt = 0; mt < 4; mt++)
#pragma unroll
        for (int nt = 0; nt < 4; nt++) {
            int row = m0 + wm * 64 + mt * 16 + g;
            int col = wn * 32 + nt * 8 + 2 * c;
            float2 v0 = make_float2(acc[mt][nt][0], acc[mt][nt][1]);
            float2 v1 = make_float2(acc[mt][nt][2], acc[mt][nt][3]);
            *(float2*)&Cb[(size_t)row * D_DIM + col]       = v0;
            *(float2*)&Cb[(size_t)(row + 8) * D_DIM + col] = v1;
        }
#undef LOAD_TILE
#undef STORE_TILE
}

// ---------------------------------------------------------------------------
// K2 (fp16-limb mma + ldmatrix): attn = softmax(scale * Q @ MK^T)
// CTA = 32 Q-rows x 1024 cols, 256 threads = 8 warps (32-col strip each per
// 256-col chunk). MK native [n][k] layout feeds the col-operand directly.
// ---------------------------------------------------------------------------
#define QP2 72   // halves per row (144 B, 16B-aligned, conflict-free)
#define K2_SMEM_BYTES ((2 * 32 * QP2 + 2 * 256 * QP2) * 2)   // 82,944

__global__ __launch_bounds__(256, 1) void scores_softmax_tc(
    const float* __restrict__ Q,
    const float* __restrict__ MK,
    float* __restrict__ attn)
{
    extern __shared__ __half smh[];
    __half* Qh = smh;                   // [32][QP2]
    __half* Ql = Qh + 32 * QP2;
    __half* Bh = Ql + 32 * QP2;         // [256][QP2]
    __half* Bl = Bh + 256 * QP2;
    __shared__ float red[8][32];

    const int t    = threadIdx.x;
    const int wid  = t >> 5;
    const int lane = t & 31;
    const int g    = lane >> 2;
    const int c    = lane & 3;

    const int bh   = blockIdx.y;
    const int row0 = blockIdx.x * 32;

    const float* Qb  = Q  + (size_t)bh * S_LEN * D_DIM;
    const float* MKb = MK + (size_t)bh * S_LEN * D_DIM;

    // ---- load Q 32x64, scale, split ----
#pragma unroll
    for (int p = 0; p < 2; p++) {
        int idx = p * 256 + t;
        int r = idx >> 4, c4 = idx & 15;
        float4 v = *(const float4*)&Qb[(size_t)(row0 + r) * D_DIM + c4 * 4];
        __half h0,h1,h2,h3,l0,l1,l2,l3;
        split2h(v.x * 0.125f, h0, l0); split2h(v.y * 0.125f, h1, l1);
        split2h(v.z * 0.125f, h2, l2); split2h(v.w * 0.125f, h3, l3);
        *(uint32_t*)&Qh[r * QP2 + c4 * 4]     = h2u(h0, h1);
        *(uint32_t*)&Qh[r * QP2 + c4 * 4 + 2] = h2u(h2, h3);
        *(uint32_t*)&Ql[r * QP2 + c4 * 4]     = h2u(l0, l1);
        *(uint32_t*)&Ql[r * QP2 + c4 * 4 + 2] = h2u(l2, l3);
    }
    __syncthreads();

    // ldmatrix addresses
    uint32_t q_addr[2][2], mb_addr[2][4];
    {
        const uint32_t q0 = smem_u32(Qh);
        const uint32_t b0a = smem_u32(Bh);
        const uint32_t limbQ = 32 * QP2 * 2;
        const uint32_t limbB = 256 * QP2 * 2;
#pragma unroll
        for (int l = 0; l < 2; l++)
#pragma unroll
            for (int mt = 0; mt < 2; mt++) {
                int row = mt * 16 + (lane & 15);
                q_addr[l][mt] = q0 + l * limbQ + (row * QP2 + (lane >> 4) * 8) * 2;
            }
#pragma unroll
        for (int l = 0; l < 2; l++)
#pragma unroll
            for (int nt = 0; nt < 4; nt++) {
                int n = wid * 32 + nt * 8 + (lane & 7);
                mb_addr[l][nt] = b0a + l * limbB + (n * QP2 + ((lane >> 3) & 1) * 8) * 2;
            }
    }

    float acc[4][2][4][4];   // [chunk][mt][nt][reg]
#pragma unroll
    for (int i = 0; i < 4; i++)
#pragma unroll
        for (int j = 0; j < 2; j++)
#pragma unroll
            for (int q = 0; q < 4; q++)
#pragma unroll
                for (int r = 0; r < 4; r++) acc[i][j][q][r] = 0.0f;

    for (int nc = 0; nc < 4; nc++) {
        // load MK rows [nc*256, +256): native [n][k] layout, split
#pragma unroll
        for (int p = 0; p < 16; p++) {
            int idx = p * 256 + t;
            int r = idx >> 4, c4 = idx & 15;
            float4 v = *(const float4*)&MKb[(size_t)(nc * 256 + r) * D_DIM + c4 * 4];
            __half h0,h1,h2,h3,l0,l1,l2,l3;
            split2h(v.x, h0, l0); split2h(v.y, h1, l1);
            split2h(v.z, h2, l2); split2h(v.w, h3, l3);
            *(uint32_t*)&Bh[r * QP2 + c4 * 4]     = h2u(h0, h1);
            *(uint32_t*)&Bh[r * QP2 + c4 * 4 + 2] = h2u(h2, h3);
            *(uint32_t*)&Bl[r * QP2 + c4 * 4]     = h2u(l0, l1);
            *(uint32_t*)&Bl[r * QP2 + c4 * 4 + 2] = h2u(l2, l3);
        }
        __syncthreads();

#pragma unroll
        for (int ks = 0; ks < 4; ks++) {
            const uint32_t koffB = ks * 16 * 2;   // bytes
            uint32_t a[2][2][4];
            uint32_t b[2][4][2];
#pragma unroll
            for (int l = 0; l < 2; l++)
#pragma unroll
                for (int mt = 0; mt < 2; mt++)
                    LDMX4(a[l][mt], q_addr[l][mt] + koffB);
#pragma unroll
            for (int l = 0; l < 2; l++)
#pragma unroll
                for (int nt = 0; nt < 4; nt++)
                    LDMX2(b[l][nt], mb_addr[l][nt] + koffB);
#pragma unroll
            for (int mt = 0; mt < 2; mt++)
#pragma unroll
                for (int nt = 0; nt < 4; nt++) {
                    MMA_F16(acc[nc][mt][nt], a[0][mt], b[0][nt]);
                    MMA_F16(acc[nc][mt][nt], a[0][mt], b[1][nt]);
                    MMA_F16(acc[nc][mt][nt], a[1][mt], b[0][nt]);
                }
        }
        __syncthreads();
    }

    // ---- softmax: rows per thread: mt*16+g (regs 0,1) and mt*16+g+8 (2,3) ----
    float fmax[2][2], fsum[2][2];
#pragma unroll
    for (int mt = 0; mt < 2; mt++)
#pragma unroll
        for (int h = 0; h < 2; h++) {
            float m = -1e30f;
#pragma unroll
            for (int nc = 0; nc < 4; nc++)
#pragma unroll
                for (int nt = 0; nt < 4; nt++) {
                    m = fmaxf(m, acc[nc][mt][nt][h * 2]);
                    m = fmaxf(m, acc[nc][mt][nt][h * 2 + 1]);
                }
            m = fmaxf(m, __shfl_xor_sync(0xFFFFFFFF, m, 1));
            m = fmaxf(m, __shfl_xor_sync(0xFFFFFFFF, m, 2));
            fmax[mt][h] = m;
        }
    if (c == 0) {
#pragma unroll
        for (int mt = 0; mt < 2; mt++)
#pragma unroll
            for (int h = 0; h < 2; h++)
                red[wid][mt * 16 + h * 8 + g] = fmax[mt][h];
    }
    __syncthreads();
#pragma unroll
    for (int mt = 0; mt < 2; mt++)
#pragma unroll
        for (int h = 0; h < 2; h++) {
            int row = mt * 16 + h * 8 + g;
            float m = red[0][row];
#pragma unroll
            for (int w = 1; w < 8; w++) m = fmaxf(m, red[w][row]);
            fmax[mt][h] = m;
        }
    __syncthreads();

    // exp + sum
#pragma unroll
    for (int mt = 0; mt < 2; mt++)
#pragma unroll
        for (int h = 0; h < 2; h++) {
            float s = 0.0f;
            float m = fmax[mt][h];
#pragma unroll
            for (int nc = 0; nc < 4; nc++)
#pragma unroll
                for (int nt = 0; nt < 4; nt++) {
                    float e0 = __expf(acc[nc][mt][nt][h * 2] - m);
                    float e1 = __expf(acc[nc][mt][nt][h * 2 + 1] - m);
                    acc[nc][mt][nt][h * 2]     = e0;
                    acc[nc][mt][nt][h * 2 + 1] = e1;
                    s += e0 + e1;
                }
            s += __shfl_xor_sync(0xFFFFFFFF, s, 1);
            s += __shfl_xor_sync(0xFFFFFFFF, s, 2);
            fsum[mt][h] = s;
        }
    if (c == 0) {
#pragma unroll
        for (int mt = 0; mt < 2; mt++)
#pragma unroll
            for (int h = 0; h < 2; h++)
                red[wid][mt * 16 + h * 8 + g] = fsum[mt][h];
    }
    __syncthreads();
#pragma unroll
    for (int mt = 0; mt < 2; mt++)
#pragma unroll
        for (int h = 0; h < 2; h++) {
            int row = mt * 16 + h * 8 + g;
            float s = red[0][row];
#pragma unroll
            for (int w = 1; w < 8; w++) s += red[w][row];
            fsum[mt][h] = 1.0f / s;
        }

    // ---- write attn ----
    float* attnb = attn + ((size_t)bh * S_LEN + row0) * S_LEN;
#pragma unroll
    for (int nc = 0; nc < 4; nc++)
#pragma unroll
        for (int mt = 0; mt < 2; mt++)
#pragma unroll
            for (int nt = 0; nt < 4; nt++) {
                int col = nc * 256 + wid * 32 + nt * 8 + 2 * c;
                int r0 = mt * 16 + g;
                float2 v0 = make_float2(acc[nc][mt][nt][0] * fsum[mt][0],
                                        acc[nc][mt][nt][1] * fsum[mt][0]);
                float2 v1 = make_float2(acc[nc][mt][nt][2] * fsum[mt][1],
                                        acc[nc][mt][nt][3] * fsum[mt][1]);
                *(float2*)&attnb[(size_t)r0 * S_LEN + col]       = v0;
                *(float2*)&attnb[(size_t)(r0 + 8) * S_LEN + col] = v1;
            }
}

// ---------------------------------------------------------------------------
extern "C" void kernel_launch(void* const* d_in, const int* in_sizes, int n_in,
                              void* d_out, int out_size)
{
    const float* Q    = (const float*)d_in[0];
    const float* Kt   = (const float*)d_in[1];
    const float* V    = (const float*)d_in[2];
    const float* mask = (const float*)d_in[3];

    float* ctx  = (float*)d_out;                                  // [BH,1024,64]
    float* attn = ctx + (size_t)BH * S_LEN * D_DIM;               // [BH,1024,1024]

    void* mkptr = nullptr;
    cudaGetSymbolAddress(&mkptr, g_MK);
    float* MK = (float*)mkptr;

    cudaFuncSetAttribute(scores_softmax_tc,
                         cudaFuncAttributeMaxDynamicSharedMemorySize,
                         K2_SMEM_BYTES);

    // K1: MK = mask @ K
    gemm_tc_kernel<<<dim3(8, BH), 128>>>(mask, Kt, MK);
    // K2: attn = softmax(scale * Q @ MK^T)
    scores_softmax_tc<<<dim3(32, BH), 256, K2_SMEM_BYTES>>>(Q, MK, attn);
    // K3: ctx = attn @ V
    gemm_tc_kernel<<<dim3(8, BH), 128>>>(attn, V, ctx);
}